// round 15
// baseline (speedup 1.0000x reference)
#include <cuda_runtime.h>
#include <math.h>
#include <float.h>
#include <limits.h>

#define NN  20000
#define MM  4
#define DD  64
#define NHH 4
#define NLL 2
#define EE  320000
#define ETOT (EE + NN)
#define FF  (NHH * DD)   // 256
#define NBIN 1024

// ------------------------- scratch (static device globals) -------------------
__device__ float g_x[2][NN * DD];
__device__ float g_xl[NN * FF];      // GAT source transform; reused as KEY[N,256]
__device__ float g_xr[NN * FF];      // GAT target transform; reused as Q[N,64]
__device__ int   g_cnt[NN];
__device__ int   g_ptr[NN + 1];
__device__ int   g_ofs[NN];
__device__ int   g_csrc[ETOT];
__device__ int   g_bins[NBIN];
__device__ int   g_binofs[NBIN];
__device__ int   g_perm[NN];         // nodes sorted by in-degree

__device__ __forceinline__ float gelu_exact(float v) {
    return 0.5f * v * (1.0f + erff(v * 0.70710678118654752f));
}

// =========================== CSR build =======================================
__global__ void k_count(const int* __restrict__ dst)
{
    int e = blockIdx.x * blockDim.x + threadIdx.x;
    if (e >= ETOT) return;
    int t = e < EE ? dst[e] : e - EE;
    atomicAdd(&g_cnt[t], 1);
}

__global__ void k_scan()
{
    __shared__ int s[1024];
    int t = threadIdx.x;
    int base = t * 20;
    int partial = 0;
    #pragma unroll
    for (int j = 0; j < 20; j++) {
        int idx = base + j;
        if (idx < NN) partial += g_cnt[idx];
    }
    s[t] = partial;
    __syncthreads();
    for (int off = 1; off < 1024; off <<= 1) {
        int v = (t >= off) ? s[t - off] : 0;
        __syncthreads();
        s[t] += v;
        __syncthreads();
    }
    int run = s[t] - partial;
    #pragma unroll
    for (int j = 0; j < 20; j++) {
        int idx = base + j;
        if (idx < NN) {
            g_ptr[idx] = run;
            g_ofs[idx] = run;
            run += g_cnt[idx];
        }
    }
    if (t == 0) g_ptr[NN] = ETOT;
}

__global__ void k_scatter(const int* __restrict__ src, const int* __restrict__ dst)
{
    int e = blockIdx.x * blockDim.x + threadIdx.x;
    if (e >= ETOT) return;
    int s, t;
    if (e < EE) { s = src[e]; t = dst[e]; }
    else        { s = t = e - EE; }
    int pos = atomicAdd(&g_ofs[t], 1);
    g_csrc[pos] = s;
}

// ---------- degree-sort permutation (counting sort) ----------
__global__ void k_hist()
{
    int i = blockIdx.x * blockDim.x + threadIdx.x;
    if (i >= NN) return;
    int deg = g_cnt[i];
    if (deg > NBIN - 1) deg = NBIN - 1;
    atomicAdd(&g_bins[deg], 1);
}

__global__ void k_binscan()
{
    __shared__ int s[NBIN];
    int t = threadIdx.x;
    int v = g_bins[t];
    s[t] = v;
    __syncthreads();
    for (int off = 1; off < NBIN; off <<= 1) {
        int u = (t >= off) ? s[t - off] : 0;
        __syncthreads();
        s[t] += u;
        __syncthreads();
    }
    g_binofs[t] = s[t] - v;   // exclusive prefix
}

__global__ void k_permscatter()
{
    int i = blockIdx.x * blockDim.x + threadIdx.x;
    if (i >= NN) return;
    int deg = g_cnt[i];
    if (deg > NBIN - 1) deg = NBIN - 1;
    int pos = atomicAdd(&g_binofs[deg], 1);
    g_perm[pos] = i;
}

// =========================== K1: encoders + fusion (R10 best: 16/block) ======
#define ENC_SMEM_F (576 + 8320 + 4160 + 4 * 196)
__global__ void k_encode(const float* __restrict__ xin,
                         const float* __restrict__ ew1, const float* __restrict__ eb1,
                         const float* __restrict__ ew2, const float* __restrict__ eb2,
                         const float* __restrict__ fw,  const float* __restrict__ fb,
                         float* __restrict__ z_out)
{
    extern __shared__ float sm[];
    float* s_ew1  = sm;            // 128
    float* s_eb1  = sm + 128;      // 128
    float* s_eb2  = sm + 256;      // 256
    float* s_fb   = sm + 512;      // 64
    float* s_ew2T = sm + 576;      // 8320: [(m*32+j)*65 + d]
    float* s_fwT  = sm + 8896;     // 4160: [k*65 + d]
    float* s_grp  = sm + 13056;    // 4 * 196

    int tid = threadIdx.x;
    int g = tid >> 6, lt = tid & 63;
    for (int i = tid; i < 128; i += 256) { s_ew1[i] = ew1[i]; s_eb1[i] = eb1[i]; }
    for (int i = tid; i < 256; i += 256) s_eb2[i] = eb2[i];
    if (tid < 64) s_fb[tid] = fb[tid];
    for (int i = tid; i < 8192; i += 256) {
        int m = i >> 11, rem = i & 2047, d = rem >> 5, j = rem & 31;
        s_ew2T[(m * 32 + j) * 65 + d] = ew2[i];
    }
    for (int i = tid; i < 4096; i += 256) {
        int d = i >> 6, k = i & 63;
        s_fwT[k * 65 + d] = fw[i];
    }
    __syncthreads();

    float* sx  = s_grp + g * 196;
    float* sh  = sx + 4;
    float* szm = sx + 132;

    for (int it = 0; it < 4; it++) {
        int n = blockIdx.x * 16 + it * 4 + g;
        bool valid = (n < NN);
        if (valid && lt < 4) sx[lt] = xin[n * MM + lt];
        __syncthreads();
        if (valid) {
            #pragma unroll
            for (int r = 0; r < 2; r++) {
                int idx = lt + 64 * r;
                int m = idx >> 5;
                sh[idx] = gelu_exact(sx[m] * s_ew1[idx] + s_eb1[idx]);
            }
        }
        __syncthreads();
        if (valid) {
            float zm = 0.f;
            #pragma unroll
            for (int m = 0; m < MM; m++) {
                float acc = s_eb2[m * 64 + lt];
                #pragma unroll
                for (int j = 0; j < 32; j++)
                    acc += sh[m * 32 + j] * s_ew2T[(m * 32 + j) * 65 + lt];
                z_out[(size_t)n * 256 + m * 64 + lt] = acc;
                zm += acc;
            }
            szm[lt] = zm * 0.25f;
        }
        __syncthreads();
        if (valid) {
            float acc = s_fb[lt];
            #pragma unroll
            for (int k = 0; k < 64; k++) acc += szm[k] * s_fwT[k * 65 + lt];
            g_x[0][n * 64 + lt] = acc;
        }
        __syncthreads();
    }
}

// =========================== K2: GAT linears (R10/R7 fused best) =============
#define LIN_SMEM_F (16448 * 2 + 4096)
__global__ void k_lin(int xsel,
                      const float* __restrict__ wl, const float* __restrict__ bl,
                      const float* __restrict__ wr, const float* __restrict__ br)
{
    extern __shared__ float sm[];
    float* swl = sm;              // [k*257 + o]
    float* swr = sm + 16448;
    float* sx  = sm + 32896;      // 64x64
    int tid = threadIdx.x;
    int nb = blockIdx.x * 64;
    int nvalid = NN - nb; if (nvalid > 64) nvalid = 64;
    for (int i = tid; i < 16384; i += 256) {
        int o = i >> 6, k = i & 63;
        swl[k * 257 + o] = wl[i];
        swr[k * 257 + o] = wr[i];
    }
    const float* xsrc = g_x[xsel] + (size_t)nb * 64;
    for (int i = tid; i < nvalid * 64; i += 256) sx[i] = xsrc[i];
    __syncthreads();

    int o = tid;
    float blv = bl[o], brv = br[o];
    #pragma unroll
    for (int c = 0; c < 8; c++) {
        if (c * 8 >= nvalid) break;
        float aL[8], aR[8];
        #pragma unroll
        for (int i = 0; i < 8; i++) { aL[i] = 0.f; aR[i] = 0.f; }
        for (int k = 0; k < 64; k++) {
            float w1 = swl[k * 257 + o];
            float w2 = swr[k * 257 + o];
            #pragma unroll
            for (int i = 0; i < 8; i++) {
                float xv = sx[(c * 8 + i) * 64 + k];
                aL[i] += xv * w1;
                aR[i] += xv * w2;
            }
        }
        #pragma unroll
        for (int i = 0; i < 8; i++) {
            int node = nb + c * 8 + i;
            if (node < NN) {
                size_t row = (size_t)node * FF;
                g_xl[row + o] = aL[i] + blv;
                g_xr[row + o] = aR[i] + brv;
            }
        }
    }
}

// =========================== K3: fused GAT edge phase (degree-sorted) ========
#define GAT_EDGE(idx, DEN_, A0x,A0y,A0z,A0w, A1x,A1y,A1z,A1w)                  \
    {                                                                          \
        int s_ = g_csrc[idx];                                                  \
        const float4* xl4_ = (const float4*)(g_xl + (size_t)s_ * FF);          \
        float4 l0 = xl4_[lane * 2];                                            \
        float4 l1 = xl4_[lane * 2 + 1];                                        \
        float p = 0.f, e_;                                                     \
        e_ = l0.x + xr0.x; p += fmaxf(e_, 0.2f * e_) * av0.x;                  \
        e_ = l0.y + xr0.y; p += fmaxf(e_, 0.2f * e_) * av0.y;                  \
        e_ = l0.z + xr0.z; p += fmaxf(e_, 0.2f * e_) * av0.z;                  \
        e_ = l0.w + xr0.w; p += fmaxf(e_, 0.2f * e_) * av0.w;                  \
        e_ = l1.x + xr1.x; p += fmaxf(e_, 0.2f * e_) * av1.x;                  \
        e_ = l1.y + xr1.y; p += fmaxf(e_, 0.2f * e_) * av1.y;                  \
        e_ = l1.z + xr1.z; p += fmaxf(e_, 0.2f * e_) * av1.z;                  \
        e_ = l1.w + xr1.w; p += fmaxf(e_, 0.2f * e_) * av1.w;                  \
        p += __shfl_xor_sync(0xffffffffu, p, 1);                               \
        p += __shfl_xor_sync(0xffffffffu, p, 2);                               \
        p += __shfl_xor_sync(0xffffffffu, p, 4);                               \
        float pe_ = __expf(p);                                                 \
        DEN_ += pe_;                                                           \
        A0x += pe_ * l0.x; A0y += pe_ * l0.y;                                  \
        A0z += pe_ * l0.z; A0w += pe_ * l0.w;                                  \
        A1x += pe_ * l1.x; A1y += pe_ * l1.y;                                  \
        A1z += pe_ * l1.z; A1w += pe_ * l1.w;                                  \
    }

__global__ void k_gat(const float* __restrict__ att, const float* __restrict__ bias,
                      int xsel, int dsel)
{
    int widx = blockIdx.x * 8 + (threadIdx.x >> 5);
    if (widx >= NN) return;
    int node = g_perm[widx];          // degree-sorted: warps in a block have ~equal work
    int lane = threadIdx.x & 31;

    const float4* xr4 = (const float4*)(g_xr + (size_t)node * FF);
    float4 xr0 = xr4[lane * 2];
    float4 xr1 = xr4[lane * 2 + 1];
    const float4* a4 = (const float4*)att;
    float4 av0 = a4[lane * 2];
    float4 av1 = a4[lane * 2 + 1];

    float dA = 0.f;
    float a0x = 0.f, a0y = 0.f, a0z = 0.f, a0w = 0.f;
    float a1x = 0.f, a1y = 0.f, a1z = 0.f, a1w = 0.f;
    float dB = 0.f;
    float b0x = 0.f, b0y = 0.f, b0z = 0.f, b0w = 0.f;
    float b1x = 0.f, b1y = 0.f, b1z = 0.f, b1w = 0.f;

    int beg = g_ptr[node], end = g_ptr[node + 1];
    int i = beg;
    for (; i + 1 < end; i += 2) {
        GAT_EDGE(i,     dA, a0x,a0y,a0z,a0w, a1x,a1y,a1z,a1w)
        GAT_EDGE(i + 1, dB, b0x,b0y,b0z,b0w, b1x,b1y,b1z,b1w)
    }
    if (i < end) {
        GAT_EDGE(i, dA, a0x,a0y,a0z,a0w, a1x,a1y,a1z,a1w)
    }

    float den = dA + dB;
    float inv = 1.f / (den + 1e-16f);
    float v[8];
    v[0] = (a0x + b0x) * inv; v[1] = (a0y + b0y) * inv;
    v[2] = (a0z + b0z) * inv; v[3] = (a0w + b0w) * inv;
    v[4] = (a1x + b1x) * inv; v[5] = (a1y + b1y) * inv;
    v[6] = (a1z + b1z) * inv; v[7] = (a1w + b1w) * inv;
    #pragma unroll
    for (int q = 0; q < 8; q++) {
        v[q] += __shfl_xor_sync(0xffffffffu, v[q], 8);
        v[q] += __shfl_xor_sync(0xffffffffu, v[q], 16);
    }
    if (lane < 8) {
        float o[8];
        const float* bs = bias + lane * 8;
        #pragma unroll
        for (int q = 0; q < 8; q++)
            o[q] = gelu_exact(0.25f * v[q] + bs[q]);
        float4* dst4 = (float4*)(g_x[dsel] + (size_t)node * DD + lane * 8);
        dst4[0] = make_float4(o[0], o[1], o[2], o[3]);
        dst4[1] = make_float4(o[4], o[5], o[6], o[7]);
    }
}

// =========================== K4: Q = x@qw^T + qb -> g_xr (flat [N,64]) =======
#define Q_SMEM_F (4160 + 2048)
__global__ void k_q(int xsel, const float* __restrict__ qw,
                    const float* __restrict__ qb)
{
    extern __shared__ float sm[];
    float* swq = sm;          // [k*65 + o]
    float* sx  = sm + 4160;   // 32 x 64
    int tid = threadIdx.x;
    int o = tid & 63, g = tid >> 6;
    int nb = blockIdx.x * 32;
    for (int i = tid; i < 4096; i += 256) {
        int d = i >> 6, k = i & 63;
        swq[k * 65 + d] = qw[i];
    }
    const float* xsrc = g_x[xsel] + (size_t)nb * 64;
    for (int i = tid; i < 2048; i += 256) sx[i] = xsrc[i];
    __syncthreads();

    float bv = qb[o];
    float a[8];
    #pragma unroll
    for (int i = 0; i < 8; i++) a[i] = 0.f;
    for (int k = 0; k < 64; k++) {
        float w = swq[k * 65 + o];
        #pragma unroll
        for (int i = 0; i < 8; i++)
            a[i] += sx[(g * 8 + i) * 64 + k] * w;
    }
    #pragma unroll
    for (int i = 0; i < 8; i++)
        g_xr[(size_t)(nb + g * 8 + i) * 64 + o] = a[i] + bv;
}

// =========================== K5: KEY = z_m@kw_m^T + kb -> g_xl [N,256] =======
#define KEY_SMEM_F (16448 + 8192)
__global__ void k_key(const float* __restrict__ kw, const float* __restrict__ kb,
                      const float* __restrict__ z)
{
    extern __shared__ float sm[];
    float* sw = sm;           // [d*257 + (m*64+e)]
    float* sz = sm + 16448;   // 32 x 256
    int tid = threadIdx.x;
    int o = tid;
    int nb = blockIdx.x * 32;
    for (int i = tid; i < 16384; i += 256) {
        int d = i & 63;
        int me = i >> 6;      // m*64 + e
        sw[d * 257 + me] = kw[i];
    }
    const float* zsrc = z + (size_t)nb * 256;
    for (int i = tid; i < 8192; i += 256) sz[i] = zsrc[i];
    __syncthreads();

    float bv = kb[o];
    int mbase = (o >> 6) << 6;
    #pragma unroll
    for (int c = 0; c < 4; c++) {
        float a[8];
        #pragma unroll
        for (int i = 0; i < 8; i++) a[i] = 0.f;
        for (int k = 0; k < 64; k++) {
            float w = sw[k * 257 + o];
            #pragma unroll
            for (int i = 0; i < 8; i++)
                a[i] += sz[(c * 8 + i) * 256 + mbase + k] * w;
        }
        #pragma unroll
        for (int i = 0; i < 8; i++)
            g_xl[(size_t)(nb + c * 8 + i) * 256 + o] = a[i] + bv;
    }
}

// =========================== K6: scores/softmax/fused/heads ==================
#define FIN_SMEM_F (2112 + 2112 + 32 + 32 + 32 + 32 + 2 + 8 * 64)
__global__ void k_fin(const float* __restrict__ z,
                      const float* __restrict__ rw1, const float* __restrict__ rb1,
                      const float* __restrict__ rw2, const float* __restrict__ rb2,
                      const float* __restrict__ uw1, const float* __restrict__ ub1,
                      const float* __restrict__ uw2, const float* __restrict__ ub2,
                      float* __restrict__ risk, float* __restrict__ unc,
                      float* __restrict__ attn)
{
    extern __shared__ float sm[];
    float* s_rw1T = sm;            // 2112: [k*33 + j]
    float* s_uw1T = sm + 2112;     // 2112
    float* s_rw2  = sm + 4224;     // 32
    float* s_uw2  = sm + 4256;     // 32
    float* s_rb1  = sm + 4288;     // 32
    float* s_ub1  = sm + 4320;     // 32
    float* s_sc2  = sm + 4352;     // 2
    float* s_fu   = sm + 4354;     // 8 * 64

    int tid = threadIdx.x;
    int w = tid >> 5, lane = tid & 31;

    for (int i = tid; i < 2048; i += 256) {
        int j = i >> 6, k = i & 63;
        s_rw1T[k * 33 + j] = rw1[i];
        s_uw1T[k * 33 + j] = uw1[i];
    }
    if (tid < 32) {
        s_rw2[tid] = rw2[tid]; s_uw2[tid] = uw2[tid];
        s_rb1[tid] = rb1[tid]; s_ub1[tid] = ub1[tid];
    }
    if (tid == 0) { s_sc2[0] = rb2[0]; s_sc2[1] = ub2[0]; }
    __syncthreads();

    int m = lane >> 3, sub = lane & 7;
    for (int it = 0; it < 4; it++) {
        int node = blockIdx.x * 32 + w * 4 + it;   // NN % 32 == 0: always valid
        const float4* q4 = (const float4*)(g_xr + (size_t)node * 64);
        const float4* k4 = (const float4*)(g_xl + (size_t)node * 256 + m * 64);
        float4 qa = q4[sub * 2], qb_ = q4[sub * 2 + 1];
        float4 ka = k4[sub * 2], kb_ = k4[sub * 2 + 1];
        float p = qa.x * ka.x + qa.y * ka.y + qa.z * ka.z + qa.w * ka.w
                + qb_.x * kb_.x + qb_.y * kb_.y + qb_.z * kb_.z + qb_.w * kb_.w;
        p += __shfl_xor_sync(0xffffffffu, p, 1);
        p += __shfl_xor_sync(0xffffffffu, p, 2);
        p += __shfl_xor_sync(0xffffffffu, p, 4);
        float s0 = __shfl_sync(0xffffffffu, p, 0)  * 0.125f;
        float s1 = __shfl_sync(0xffffffffu, p, 8)  * 0.125f;
        float s2 = __shfl_sync(0xffffffffu, p, 16) * 0.125f;
        float s3 = __shfl_sync(0xffffffffu, p, 24) * 0.125f;
        float mx = fmaxf(fmaxf(s0, s1), fmaxf(s2, s3));
        float e0 = expf(s0 - mx), e1 = expf(s1 - mx);
        float e2 = expf(s2 - mx), e3 = expf(s3 - mx);
        float inv = 1.f / (e0 + e1 + e2 + e3);
        float at0 = e0 * inv, at1 = e1 * inv, at2 = e2 * inv, at3 = e3 * inv;
        if (lane < 4) {
            float av = (lane == 0) ? at0 : (lane == 1) ? at1 : (lane == 2) ? at2 : at3;
            attn[node * 4 + lane] = av;
        }
        const float* zr = z + (size_t)node * 256;
        float f0 = at0 * zr[lane]       + at1 * zr[64 + lane]
                 + at2 * zr[128 + lane] + at3 * zr[192 + lane];
        float f1 = at0 * zr[32 + lane]  + at1 * zr[96 + lane]
                 + at2 * zr[160 + lane] + at3 * zr[224 + lane];
        s_fu[w * 64 + lane] = f0;
        s_fu[w * 64 + 32 + lane] = f1;
        __syncwarp();
        float hr = s_rb1[lane], hu = s_ub1[lane];
        const float* fu = s_fu + w * 64;
        #pragma unroll
        for (int k = 0; k < 64; k++) {
            float fv = fu[k];
            hr += fv * s_rw1T[k * 33 + lane];
            hu += fv * s_uw1T[k * 33 + lane];
        }
        hr = gelu_exact(hr) * s_rw2[lane];
        hu = gelu_exact(hu) * s_uw2[lane];
        #pragma unroll
        for (int off = 16; off; off >>= 1) {
            hr += __shfl_xor_sync(0xffffffffu, hr, off);
            hu += __shfl_xor_sync(0xffffffffu, hu, off);
        }
        if (lane == 0) {
            risk[node] = hr + s_sc2[0];
            float uv = hu + s_sc2[1];
            unc[node] = 1.f / (1.f + expf(-uv));
        }
        __syncwarp();
    }
}

// =========================== launch ==========================================
extern "C" void kernel_launch(void* const* d_in, const int* in_sizes, int n_in,
                              void* d_out, int out_size)
{
    const float* xmm  = (const float*)d_in[0];
    const int*   ei   = (const int*)  d_in[1];
    const float* ew1  = (const float*)d_in[2];
    const float* eb1  = (const float*)d_in[3];
    const float* ew2  = (const float*)d_in[4];
    const float* eb2  = (const float*)d_in[5];
    const float* fw   = (const float*)d_in[6];
    const float* fb   = (const float*)d_in[7];
    const float* gwl  = (const float*)d_in[8];
    const float* gbl  = (const float*)d_in[9];
    const float* gwr  = (const float*)d_in[10];
    const float* gbr  = (const float*)d_in[11];
    const float* gatt = (const float*)d_in[12];
    const float* gbia = (const float*)d_in[13];
    const float* qw   = (const float*)d_in[14];
    const float* qb   = (const float*)d_in[15];
    const float* kw   = (const float*)d_in[16];
    const float* kb   = (const float*)d_in[17];
    const float* rw1  = (const float*)d_in[18];
    const float* rb1  = (const float*)d_in[19];
    const float* rw2  = (const float*)d_in[20];
    const float* rb2  = (const float*)d_in[21];
    const float* uw1  = (const float*)d_in[22];
    const float* ub1  = (const float*)d_in[23];
    const float* uw2  = (const float*)d_in[24];
    const float* ub2  = (const float*)d_in[25];

    float* out    = (float*)d_out;
    float* o_risk = out;
    float* o_unc  = out + NN;
    float* o_attn = out + 2 * NN;
    float* o_z    = out + 2 * NN + NN * MM;

    const int* src = ei;
    const int* dst = ei + EE;

    cudaFuncSetAttribute(k_encode, cudaFuncAttributeMaxDynamicSharedMemorySize,
                         ENC_SMEM_F * 4);
    cudaFuncSetAttribute(k_lin, cudaFuncAttributeMaxDynamicSharedMemorySize,
                         LIN_SMEM_F * 4);
    cudaFuncSetAttribute(k_key, cudaFuncAttributeMaxDynamicSharedMemorySize,
                         KEY_SMEM_F * 4);

    // CSR build (edge set is layer-independent)
    void* cnt_ptr = nullptr;
    void* bins_ptr = nullptr;
    cudaGetSymbolAddress(&cnt_ptr, g_cnt);
    cudaGetSymbolAddress(&bins_ptr, g_bins);
    cudaMemsetAsync(cnt_ptr, 0, NN * sizeof(int));
    cudaMemsetAsync(bins_ptr, 0, NBIN * sizeof(int));
    k_count<<<(ETOT + 255) / 256, 256>>>(dst);
    k_scan<<<1, 1024>>>();
    k_scatter<<<(ETOT + 255) / 256, 256>>>(src, dst);
    // degree-sort permutation (uses g_cnt, independent of k_scatter)
    k_hist<<<(NN + 255) / 256, 256>>>();
    k_binscan<<<1, NBIN>>>();
    k_permscatter<<<(NN + 255) / 256, 256>>>();

    k_encode<<<(NN + 15) / 16, 256, ENC_SMEM_F * 4>>>(xmm, ew1, eb1, ew2, eb2,
                                                      fw, fb, o_z);

    int cur = 0;
    for (int l = 0; l < NLL; l++) {
        k_lin<<<(NN + 63) / 64, 256, LIN_SMEM_F * 4>>>(cur,
                               gwl + (size_t)l * FF * DD, gbl + l * FF,
                               gwr + (size_t)l * FF * DD, gbr + l * FF);
        k_gat<<<(NN + 7) / 8, 256>>>(gatt + l * NHH * DD, gbia + l * DD,
                                     cur, cur ^ 1);
        cur ^= 1;
    }

    // head path: Q -> g_xr, KEY -> g_xl (both free after last GAT), then finish
    k_q<<<NN / 32, 256, Q_SMEM_F * 4>>>(cur, qw, qb);
    k_key<<<NN / 32, 256, KEY_SMEM_F * 4>>>(kw, kb, o_z);
    k_fin<<<NN / 32, 256, FIN_SMEM_F * 4>>>(o_z, rw1, rb1, rw2, rb2,
                                            uw1, ub1, uw2, ub2,
                                            o_risk, o_unc, o_attn);
}

// round 16
// speedup vs baseline: 1.0578x; 1.0578x over previous
#include <cuda_runtime.h>
#include <math.h>
#include <float.h>
#include <limits.h>

#define NN  20000
#define MM  4
#define DD  64
#define NHH 4
#define NLL 2
#define EE  320000
#define ETOT (EE + NN)
#define FF  (NHH * DD)   // 256

// ------------------------- scratch (static device globals) -------------------
__device__ float g_x[2][NN * DD];
__device__ float g_xl[NN * FF];      // GAT source transform; reused as KEY[N,256]
__device__ float g_xr[NN * FF];      // GAT target transform; reused as Q[N,64]
__device__ float g_h[NN * 128];      // encoder hidden
__device__ int   g_cnt[NN];
__device__ int   g_ptr[NN + 1];
__device__ int   g_ofs[NN];
__device__ int   g_csrc[ETOT];

__device__ __forceinline__ float gelu_exact(float v) {
    return 0.5f * v * (1.0f + erff(v * 0.70710678118654752f));
}

// =========================== CSR build =======================================
__global__ void k_count(const int* __restrict__ dst)
{
    int e = blockIdx.x * blockDim.x + threadIdx.x;
    if (e >= ETOT) return;
    int t = e < EE ? dst[e] : e - EE;
    atomicAdd(&g_cnt[t], 1);
}

__global__ void k_scan()
{
    __shared__ int s[1024];
    int t = threadIdx.x;
    int base = t * 20;
    int partial = 0;
    #pragma unroll
    for (int j = 0; j < 20; j++) {
        int idx = base + j;
        if (idx < NN) partial += g_cnt[idx];
    }
    s[t] = partial;
    __syncthreads();
    for (int off = 1; off < 1024; off <<= 1) {
        int v = (t >= off) ? s[t - off] : 0;
        __syncthreads();
        s[t] += v;
        __syncthreads();
    }
    int run = s[t] - partial;
    #pragma unroll
    for (int j = 0; j < 20; j++) {
        int idx = base + j;
        if (idx < NN) {
            g_ptr[idx] = run;
            g_ofs[idx] = run;
            run += g_cnt[idx];
        }
    }
    if (t == 0) g_ptr[NN] = ETOT;
}

__global__ void k_scatter(const int* __restrict__ src, const int* __restrict__ dst)
{
    int e = blockIdx.x * blockDim.x + threadIdx.x;
    if (e >= ETOT) return;
    int s, t;
    if (e < EE) { s = src[e]; t = dst[e]; }
    else        { s = t = e - EE; }
    int pos = atomicAdd(&g_ofs[t], 1);
    g_csrc[pos] = s;
}

// =========================== K1a: encoder hidden =============================
__global__ void k_h(const float* __restrict__ xin,
                    const float* __restrict__ ew1, const float* __restrict__ eb1)
{
    int i = blockIdx.x * blockDim.x + threadIdx.x;
    if (i >= NN * 128) return;
    int n = i >> 7, idx = i & 127;
    int m = idx >> 5;
    g_h[i] = gelu_exact(xin[n * 4 + m] * ew1[idx] + eb1[idx]);
}

// =========================== K1b: z (block-diagonal GEMM) ====================
// 64 nodes/block, 256 threads (one output o = m*64+d each); 8-node blocking.
#define Z_SMEM_F (8224 + 8192)
__global__ void k_z(const float* __restrict__ ew2, const float* __restrict__ eb2,
                    float* __restrict__ z_out)
{
    extern __shared__ float sm[];
    float* sw = sm;           // [j*257 + o] = ew2[o*32 + j]
    float* sh = sm + 8224;    // [node_local*128 + idx]
    int tid = threadIdx.x;
    int nb = blockIdx.x * 64;
    int nvalid = NN - nb; if (nvalid > 64) nvalid = 64;
    for (int i = tid; i < 8192; i += 256) {
        int o = i >> 5, j = i & 31;
        sw[j * 257 + o] = ew2[i];
    }
    const float* hsrc = g_h + (size_t)nb * 128;
    for (int i = tid; i < nvalid * 128; i += 256) sh[i] = hsrc[i];
    __syncthreads();

    int o = tid;
    int mb = (o >> 6) << 5;   // m * 32
    float bv = eb2[o];
    #pragma unroll
    for (int c = 0; c < 8; c++) {
        if (c * 8 >= nvalid) break;
        float a[8];
        #pragma unroll
        for (int i = 0; i < 8; i++) a[i] = 0.f;
        for (int j = 0; j < 32; j++) {
            float w = sw[j * 257 + o];
            #pragma unroll
            for (int i = 0; i < 8; i++)
                a[i] += sh[(c * 8 + i) * 128 + mb + j] * w;
        }
        #pragma unroll
        for (int i = 0; i < 8; i++) {
            int node = nb + c * 8 + i;
            if (node < NN) z_out[(size_t)node * 256 + o] = a[i] + bv;
        }
    }
}

// =========================== K1c: zmean + fusion GEMM ========================
// 32 nodes/block, 256 threads = 4 groups x 64 outputs.
#define FUSE_SMEM_F (4160 + 2048)
__global__ void k_fuse(const float* __restrict__ fw, const float* __restrict__ fb,
                       const float* __restrict__ z)
{
    extern __shared__ float sm[];
    float* swf = sm;          // [k*65 + d]
    float* szm = sm + 4160;   // [i*64 + k]
    int tid = threadIdx.x;
    int nb = blockIdx.x * 32;  // NN % 32 == 0
    for (int i = tid; i < 4096; i += 256) {
        int d = i >> 6, k = i & 63;
        swf[k * 65 + d] = fw[i];
    }
    for (int i = tid; i < 2048; i += 256) {
        int node = nb + (i >> 6), k = i & 63;
        const float* zr = z + (size_t)node * 256;
        szm[i] = 0.25f * (zr[k] + zr[64 + k] + zr[128 + k] + zr[192 + k]);
    }
    __syncthreads();

    int o = tid & 63, g = tid >> 6;
    float bv = fb[o];
    float a[8];
    #pragma unroll
    for (int i = 0; i < 8; i++) a[i] = 0.f;
    for (int k = 0; k < 64; k++) {
        float w = swf[k * 65 + o];
        #pragma unroll
        for (int i = 0; i < 8; i++)
            a[i] += szm[(g * 8 + i) * 64 + k] * w;
    }
    #pragma unroll
    for (int i = 0; i < 8; i++)
        g_x[0][(size_t)(nb + g * 8 + i) * 64 + o] = a[i] + bv;
}

// =========================== K2: GAT linears (R10/R7 fused best) =============
#define LIN_SMEM_F (16448 * 2 + 4096)
__global__ void k_lin(int xsel,
                      const float* __restrict__ wl, const float* __restrict__ bl,
                      const float* __restrict__ wr, const float* __restrict__ br)
{
    extern __shared__ float sm[];
    float* swl = sm;              // [k*257 + o]
    float* swr = sm + 16448;
    float* sx  = sm + 32896;      // 64x64
    int tid = threadIdx.x;
    int nb = blockIdx.x * 64;
    int nvalid = NN - nb; if (nvalid > 64) nvalid = 64;
    for (int i = tid; i < 16384; i += 256) {
        int o = i >> 6, k = i & 63;
        swl[k * 257 + o] = wl[i];
        swr[k * 257 + o] = wr[i];
    }
    const float* xsrc = g_x[xsel] + (size_t)nb * 64;
    for (int i = tid; i < nvalid * 64; i += 256) sx[i] = xsrc[i];
    __syncthreads();

    int o = tid;
    float blv = bl[o], brv = br[o];
    #pragma unroll
    for (int c = 0; c < 8; c++) {
        if (c * 8 >= nvalid) break;
        float aL[8], aR[8];
        #pragma unroll
        for (int i = 0; i < 8; i++) { aL[i] = 0.f; aR[i] = 0.f; }
        for (int k = 0; k < 64; k++) {
            float w1 = swl[k * 257 + o];
            float w2 = swr[k * 257 + o];
            #pragma unroll
            for (int i = 0; i < 8; i++) {
                float xv = sx[(c * 8 + i) * 64 + k];
                aL[i] += xv * w1;
                aR[i] += xv * w2;
            }
        }
        #pragma unroll
        for (int i = 0; i < 8; i++) {
            int node = nb + c * 8 + i;
            if (node < NN) {
                size_t row = (size_t)node * FF;
                g_xl[row + o] = aL[i] + blv;
                g_xr[row + o] = aR[i] + brv;
            }
        }
    }
}

// =========================== K3: fused GAT edge phase (R10 2-way best) =======
#define GAT_EDGE(idx, DEN_, A0x,A0y,A0z,A0w, A1x,A1y,A1z,A1w)                  \
    {                                                                          \
        int s_ = g_csrc[idx];                                                  \
        const float4* xl4_ = (const float4*)(g_xl + (size_t)s_ * FF);          \
        float4 l0 = xl4_[lane * 2];                                            \
        float4 l1 = xl4_[lane * 2 + 1];                                        \
        float p = 0.f, e_;                                                     \
        e_ = l0.x + xr0.x; p += fmaxf(e_, 0.2f * e_) * av0.x;                  \
        e_ = l0.y + xr0.y; p += fmaxf(e_, 0.2f * e_) * av0.y;                  \
        e_ = l0.z + xr0.z; p += fmaxf(e_, 0.2f * e_) * av0.z;                  \
        e_ = l0.w + xr0.w; p += fmaxf(e_, 0.2f * e_) * av0.w;                  \
        e_ = l1.x + xr1.x; p += fmaxf(e_, 0.2f * e_) * av1.x;                  \
        e_ = l1.y + xr1.y; p += fmaxf(e_, 0.2f * e_) * av1.y;                  \
        e_ = l1.z + xr1.z; p += fmaxf(e_, 0.2f * e_) * av1.z;                  \
        e_ = l1.w + xr1.w; p += fmaxf(e_, 0.2f * e_) * av1.w;                  \
        p += __shfl_xor_sync(0xffffffffu, p, 1);                               \
        p += __shfl_xor_sync(0xffffffffu, p, 2);                               \
        p += __shfl_xor_sync(0xffffffffu, p, 4);                               \
        float pe_ = __expf(p);                                                 \
        DEN_ += pe_;                                                           \
        A0x += pe_ * l0.x; A0y += pe_ * l0.y;                                  \
        A0z += pe_ * l0.z; A0w += pe_ * l0.w;                                  \
        A1x += pe_ * l1.x; A1y += pe_ * l1.y;                                  \
        A1z += pe_ * l1.z; A1w += pe_ * l1.w;                                  \
    }

__global__ void k_gat(const float* __restrict__ att, const float* __restrict__ bias,
                      int xsel, int dsel)
{
    int node = blockIdx.x * 8 + (threadIdx.x >> 5);
    if (node >= NN) return;
    int lane = threadIdx.x & 31;

    const float4* xr4 = (const float4*)(g_xr + (size_t)node * FF);
    float4 xr0 = xr4[lane * 2];
    float4 xr1 = xr4[lane * 2 + 1];
    const float4* a4 = (const float4*)att;
    float4 av0 = a4[lane * 2];
    float4 av1 = a4[lane * 2 + 1];

    float dA = 0.f;
    float a0x = 0.f, a0y = 0.f, a0z = 0.f, a0w = 0.f;
    float a1x = 0.f, a1y = 0.f, a1z = 0.f, a1w = 0.f;
    float dB = 0.f;
    float b0x = 0.f, b0y = 0.f, b0z = 0.f, b0w = 0.f;
    float b1x = 0.f, b1y = 0.f, b1z = 0.f, b1w = 0.f;

    int beg = g_ptr[node], end = g_ptr[node + 1];
    int i = beg;
    for (; i + 1 < end; i += 2) {
        GAT_EDGE(i,     dA, a0x,a0y,a0z,a0w, a1x,a1y,a1z,a1w)
        GAT_EDGE(i + 1, dB, b0x,b0y,b0z,b0w, b1x,b1y,b1z,b1w)
    }
    if (i < end) {
        GAT_EDGE(i, dA, a0x,a0y,a0z,a0w, a1x,a1y,a1z,a1w)
    }

    float den = dA + dB;
    float inv = 1.f / (den + 1e-16f);
    float v[8];
    v[0] = (a0x + b0x) * inv; v[1] = (a0y + b0y) * inv;
    v[2] = (a0z + b0z) * inv; v[3] = (a0w + b0w) * inv;
    v[4] = (a1x + b1x) * inv; v[5] = (a1y + b1y) * inv;
    v[6] = (a1z + b1z) * inv; v[7] = (a1w + b1w) * inv;
    #pragma unroll
    for (int q = 0; q < 8; q++) {
        v[q] += __shfl_xor_sync(0xffffffffu, v[q], 8);
        v[q] += __shfl_xor_sync(0xffffffffu, v[q], 16);
    }
    if (lane < 8) {
        float o[8];
        const float* bs = bias + lane * 8;
        #pragma unroll
        for (int q = 0; q < 8; q++)
            o[q] = gelu_exact(0.25f * v[q] + bs[q]);
        float4* dst4 = (float4*)(g_x[dsel] + (size_t)node * DD + lane * 8);
        dst4[0] = make_float4(o[0], o[1], o[2], o[3]);
        dst4[1] = make_float4(o[4], o[5], o[6], o[7]);
    }
}

// =========================== K4: Q = x@qw^T + qb -> g_xr (flat [N,64]) =======
#define Q_SMEM_F (4160 + 2048)
__global__ void k_q(int xsel, const float* __restrict__ qw,
                    const float* __restrict__ qb)
{
    extern __shared__ float sm[];
    float* swq = sm;          // [k*65 + o]
    float* sx  = sm + 4160;   // 32 x 64
    int tid = threadIdx.x;
    int o = tid & 63, g = tid >> 6;
    int nb = blockIdx.x * 32;
    for (int i = tid; i < 4096; i += 256) {
        int d = i >> 6, k = i & 63;
        swq[k * 65 + d] = qw[i];
    }
    const float* xsrc = g_x[xsel] + (size_t)nb * 64;
    for (int i = tid; i < 2048; i += 256) sx[i] = xsrc[i];
    __syncthreads();

    float bv = qb[o];
    float a[8];
    #pragma unroll
    for (int i = 0; i < 8; i++) a[i] = 0.f;
    for (int k = 0; k < 64; k++) {
        float w = swq[k * 65 + o];
        #pragma unroll
        for (int i = 0; i < 8; i++)
            a[i] += sx[(g * 8 + i) * 64 + k] * w;
    }
    #pragma unroll
    for (int i = 0; i < 8; i++)
        g_xr[(size_t)(nb + g * 8 + i) * 64 + o] = a[i] + bv;
}

// =========================== K5: KEY = z_m@kw_m^T + kb -> g_xl [N,256] =======
#define KEY_SMEM_F (16448 + 8192)
__global__ void k_key(const float* __restrict__ kw, const float* __restrict__ kb,
                      const float* __restrict__ z)
{
    extern __shared__ float sm[];
    float* sw = sm;           // [d*257 + (m*64+e)]
    float* sz = sm + 16448;   // 32 x 256
    int tid = threadIdx.x;
    int o = tid;
    int nb = blockIdx.x * 32;
    for (int i = tid; i < 16384; i += 256) {
        int d = i & 63;
        int me = i >> 6;      // m*64 + e
        sw[d * 257 + me] = kw[i];
    }
    const float* zsrc = z + (size_t)nb * 256;
    for (int i = tid; i < 8192; i += 256) sz[i] = zsrc[i];
    __syncthreads();

    float bv = kb[o];
    int mbase = (o >> 6) << 6;
    #pragma unroll
    for (int c = 0; c < 4; c++) {
        float a[8];
        #pragma unroll
        for (int i = 0; i < 8; i++) a[i] = 0.f;
        for (int k = 0; k < 64; k++) {
            float w = sw[k * 257 + o];
            #pragma unroll
            for (int i = 0; i < 8; i++)
                a[i] += sz[(c * 8 + i) * 256 + mbase + k] * w;
        }
        #pragma unroll
        for (int i = 0; i < 8; i++)
            g_xl[(size_t)(nb + c * 8 + i) * 256 + o] = a[i] + bv;
    }
}

// =========================== K6: scores/softmax/fused/heads ==================
#define FIN_SMEM_F (2112 + 2112 + 32 + 32 + 32 + 32 + 2 + 8 * 64)
__global__ void k_fin(const float* __restrict__ z,
                      const float* __restrict__ rw1, const float* __restrict__ rb1,
                      const float* __restrict__ rw2, const float* __restrict__ rb2,
                      const float* __restrict__ uw1, const float* __restrict__ ub1,
                      const float* __restrict__ uw2, const float* __restrict__ ub2,
                      float* __restrict__ risk, float* __restrict__ unc,
                      float* __restrict__ attn)
{
    extern __shared__ float sm[];
    float* s_rw1T = sm;            // 2112: [k*33 + j]
    float* s_uw1T = sm + 2112;     // 2112
    float* s_rw2  = sm + 4224;     // 32
    float* s_uw2  = sm + 4256;     // 32
    float* s_rb1  = sm + 4288;     // 32
    float* s_ub1  = sm + 4320;     // 32
    float* s_sc2  = sm + 4352;     // 2
    float* s_fu   = sm + 4354;     // 8 * 64

    int tid = threadIdx.x;
    int w = tid >> 5, lane = tid & 31;

    for (int i = tid; i < 2048; i += 256) {
        int j = i >> 6, k = i & 63;
        s_rw1T[k * 33 + j] = rw1[i];
        s_uw1T[k * 33 + j] = uw1[i];
    }
    if (tid < 32) {
        s_rw2[tid] = rw2[tid]; s_uw2[tid] = uw2[tid];
        s_rb1[tid] = rb1[tid]; s_ub1[tid] = ub1[tid];
    }
    if (tid == 0) { s_sc2[0] = rb2[0]; s_sc2[1] = ub2[0]; }
    __syncthreads();

    int m = lane >> 3, sub = lane & 7;
    for (int it = 0; it < 4; it++) {
        int node = blockIdx.x * 32 + w * 4 + it;   // NN % 32 == 0: always valid
        const float4* q4 = (const float4*)(g_xr + (size_t)node * 64);
        const float4* k4 = (const float4*)(g_xl + (size_t)node * 256 + m * 64);
        float4 qa = q4[sub * 2], qb_ = q4[sub * 2 + 1];
        float4 ka = k4[sub * 2], kb_ = k4[sub * 2 + 1];
        float p = qa.x * ka.x + qa.y * ka.y + qa.z * ka.z + qa.w * ka.w
                + qb_.x * kb_.x + qb_.y * kb_.y + qb_.z * kb_.z + qb_.w * kb_.w;
        p += __shfl_xor_sync(0xffffffffu, p, 1);
        p += __shfl_xor_sync(0xffffffffu, p, 2);
        p += __shfl_xor_sync(0xffffffffu, p, 4);
        float s0 = __shfl_sync(0xffffffffu, p, 0)  * 0.125f;
        float s1 = __shfl_sync(0xffffffffu, p, 8)  * 0.125f;
        float s2 = __shfl_sync(0xffffffffu, p, 16) * 0.125f;
        float s3 = __shfl_sync(0xffffffffu, p, 24) * 0.125f;
        float mx = fmaxf(fmaxf(s0, s1), fmaxf(s2, s3));
        float e0 = expf(s0 - mx), e1 = expf(s1 - mx);
        float e2 = expf(s2 - mx), e3 = expf(s3 - mx);
        float inv = 1.f / (e0 + e1 + e2 + e3);
        float at0 = e0 * inv, at1 = e1 * inv, at2 = e2 * inv, at3 = e3 * inv;
        if (lane < 4) {
            float av = (lane == 0) ? at0 : (lane == 1) ? at1 : (lane == 2) ? at2 : at3;
            attn[node * 4 + lane] = av;
        }
        const float* zr = z + (size_t)node * 256;
        float f0 = at0 * zr[lane]       + at1 * zr[64 + lane]
                 + at2 * zr[128 + lane] + at3 * zr[192 + lane];
        float f1 = at0 * zr[32 + lane]  + at1 * zr[96 + lane]
                 + at2 * zr[160 + lane] + at3 * zr[224 + lane];
        s_fu[w * 64 + lane] = f0;
        s_fu[w * 64 + 32 + lane] = f1;
        __syncwarp();
        float hr = s_rb1[lane], hu = s_ub1[lane];
        const float* fu = s_fu + w * 64;
        #pragma unroll
        for (int k = 0; k < 64; k++) {
            float fv = fu[k];
            hr += fv * s_rw1T[k * 33 + lane];
            hu += fv * s_uw1T[k * 33 + lane];
        }
        hr = gelu_exact(hr) * s_rw2[lane];
        hu = gelu_exact(hu) * s_uw2[lane];
        #pragma unroll
        for (int off = 16; off; off >>= 1) {
            hr += __shfl_xor_sync(0xffffffffu, hr, off);
            hu += __shfl_xor_sync(0xffffffffu, hu, off);
        }
        if (lane == 0) {
            risk[node] = hr + s_sc2[0];
            float uv = hu + s_sc2[1];
            unc[node] = 1.f / (1.f + expf(-uv));
        }
        __syncwarp();
    }
}

// =========================== launch ==========================================
extern "C" void kernel_launch(void* const* d_in, const int* in_sizes, int n_in,
                              void* d_out, int out_size)
{
    const float* xmm  = (const float*)d_in[0];
    const int*   ei   = (const int*)  d_in[1];
    const float* ew1  = (const float*)d_in[2];
    const float* eb1  = (const float*)d_in[3];
    const float* ew2  = (const float*)d_in[4];
    const float* eb2  = (const float*)d_in[5];
    const float* fw   = (const float*)d_in[6];
    const float* fb   = (const float*)d_in[7];
    const float* gwl  = (const float*)d_in[8];
    const float* gbl  = (const float*)d_in[9];
    const float* gwr  = (const float*)d_in[10];
    const float* gbr  = (const float*)d_in[11];
    const float* gatt = (const float*)d_in[12];
    const float* gbia = (const float*)d_in[13];
    const float* qw   = (const float*)d_in[14];
    const float* qb   = (const float*)d_in[15];
    const float* kw   = (const float*)d_in[16];
    const float* kb   = (const float*)d_in[17];
    const float* rw1  = (const float*)d_in[18];
    const float* rb1  = (const float*)d_in[19];
    const float* rw2  = (const float*)d_in[20];
    const float* rb2  = (const float*)d_in[21];
    const float* uw1  = (const float*)d_in[22];
    const float* ub1  = (const float*)d_in[23];
    const float* uw2  = (const float*)d_in[24];
    const float* ub2  = (const float*)d_in[25];

    float* out    = (float*)d_out;
    float* o_risk = out;
    float* o_unc  = out + NN;
    float* o_attn = out + 2 * NN;
    float* o_z    = out + 2 * NN + NN * MM;

    const int* src = ei;
    const int* dst = ei + EE;

    cudaFuncSetAttribute(k_z, cudaFuncAttributeMaxDynamicSharedMemorySize,
                         Z_SMEM_F * 4);
    cudaFuncSetAttribute(k_lin, cudaFuncAttributeMaxDynamicSharedMemorySize,
                         LIN_SMEM_F * 4);
    cudaFuncSetAttribute(k_key, cudaFuncAttributeMaxDynamicSharedMemorySize,
                         KEY_SMEM_F * 4);

    // CSR build (edge set is layer-independent)
    void* cnt_ptr = nullptr;
    cudaGetSymbolAddress(&cnt_ptr, g_cnt);
    cudaMemsetAsync(cnt_ptr, 0, NN * sizeof(int));
    k_count<<<(ETOT + 255) / 256, 256>>>(dst);
    k_scan<<<1, 1024>>>();
    k_scatter<<<(ETOT + 255) / 256, 256>>>(src, dst);

    // encoder: h -> z -> fuse
    k_h<<<(NN * 128 + 255) / 256, 256>>>(xmm, ew1, eb1);
    k_z<<<(NN + 63) / 64, 256, Z_SMEM_F * 4>>>(ew2, eb2, o_z);
    k_fuse<<<NN / 32, 256, FUSE_SMEM_F * 4>>>(fw, fb, o_z);

    int cur = 0;
    for (int l = 0; l < NLL; l++) {
        k_lin<<<(NN + 63) / 64, 256, LIN_SMEM_F * 4>>>(cur,
                               gwl + (size_t)l * FF * DD, gbl + l * FF,
                               gwr + (size_t)l * FF * DD, gbr + l * FF);
        k_gat<<<(NN + 7) / 8, 256>>>(gatt + l * NHH * DD, gbia + l * DD,
                                     cur, cur ^ 1);
        cur ^= 1;
    }

    // head path: Q -> g_xr, KEY -> g_xl (both free after last GAT), then finish
    k_q<<<NN / 32, 256, Q_SMEM_F * 4>>>(cur, qw, qb);
    k_key<<<NN / 32, 256, KEY_SMEM_F * 4>>>(kw, kb, o_z);
    k_fin<<<NN / 32, 256, FIN_SMEM_F * 4>>>(o_z, rw1, rb1, rw2, rb2,
                                            uw1, ub1, uw2, ub2,
                                            o_risk, o_unc, o_attn);
}